// round 4
// baseline (speedup 1.0000x reference)
#include <cuda_runtime.h>
#include <math.h>

#define S_LEN   2048
#define BATCH   2
#define EMBED   1024
#define HEADS   16
#define HDIM    64
#define MROWS   (S_LEN * BATCH)       // 4096
#define BHEADS  (BATCH * HEADS)       // 32
#define NQKV    (3 * EMBED)           // 3072

typedef unsigned long long u64;

// ---- packed fp32x2 helpers (sm_103a FFMA2 path; bit-exact fp32) -----------
__device__ __forceinline__ u64 pack2(float lo, float hi) {
    u64 r; asm("mov.b64 %0, {%1, %2};" : "=l"(r) : "f"(lo), "f"(hi)); return r;
}
__device__ __forceinline__ void unpack2(u64 v, float& lo, float& hi) {
    asm("mov.b64 {%0, %1}, %2;" : "=f"(lo), "=f"(hi) : "l"(v));
}
__device__ __forceinline__ void ffma2(u64& d, u64 a, u64 b, u64 c) {
    asm("fma.rn.f32x2 %0, %1, %2, %3;" : "=l"(d) : "l"(a), "l"(b), "l"(c));
}
__device__ __forceinline__ void fmul2(u64& d, u64 a, u64 b) {
    asm("mul.rn.f32x2 %0, %1, %2;" : "=l"(d) : "l"(a), "l"(b));
}

// ---- cp.async helpers ------------------------------------------------------
__device__ __forceinline__ void cp_async16(void* smem, const void* gmem) {
    unsigned saddr = (unsigned)__cvta_generic_to_shared(smem);
    asm volatile("cp.async.cg.shared.global [%0], [%1], 16;"
                 :: "r"(saddr), "l"(gmem));
}
__device__ __forceinline__ void cp_commit() {
    asm volatile("cp.async.commit_group;");
}
template <int N>
__device__ __forceinline__ void cp_wait() {
    asm volatile("cp.async.wait_group %0;" :: "n"(N));
}

// Scratch (allocation-free rule: __device__ globals).
__device__ float g_Q[BHEADS * S_LEN * HDIM];
__device__ float g_K[BHEADS * S_LEN * HDIM];
__device__ float g_V[BHEADS * S_LEN * HDIM];
__device__ float g_Attn[MROWS * EMBED];   // attention output in [S,B,E] = [m,e]

// ---------------------------------------------------------------------------
// sgemm 128x128x8, 8x8 tiles via f32x2: acc = 8x4 pairs, 32 FFMA2 per kk.
// A stored in SMEM as duplicated pairs (a,a) so LDS gives FFMA2-ready operand.
// ---------------------------------------------------------------------------
#define GBM 128
#define GBN 128
#define GBK 8
#define GTM 8
#define GTN 8

// ---------------------------------------------------------------------------
// Kernel 1: QKV projection + head-major scatter (+ q scaling 0.125)
// ---------------------------------------------------------------------------
__global__ __launch_bounds__(256) void qkv_gemm_kernel(
    const float* __restrict__ X,      // [4096, 1024]
    const float* __restrict__ W,      // [3072, 1024]
    const float* __restrict__ bias)   // [3072]
{
    __shared__ float As2[GBK][2 * GBM];   // duplicated pairs
    __shared__ float Bs[GBK][GBN];

    const int tid = threadIdx.x;
    const int tx  = tid % (GBN / GTN);   // 0..15
    const int ty  = tid / (GBN / GTN);   // 0..15
    const int m0  = blockIdx.y * GBM;
    const int n0  = blockIdx.x * GBN;

    const int lrow = tid / 2;            // 0..127
    const int lcol = (tid % 2) * 4;      // 0 or 4

    u64 acc2[GTM][GTN / 2];
#pragma unroll
    for (int i = 0; i < GTM; i++)
#pragma unroll
        for (int j = 0; j < GTN / 2; j++) acc2[i][j] = 0ull;

    const float* Aload = X + (size_t)(m0 + lrow) * EMBED + lcol;
    const float* Bload = W + (size_t)(n0 + lrow) * EMBED + lcol;

    float4 av = *(const float4*)(Aload);
    float4 bv = *(const float4*)(Bload);

    for (int k0 = 0; k0 < EMBED; k0 += GBK) {
        // store staged tile (A duplicated)
        {
            float va[4] = {av.x, av.y, av.z, av.w};
            float vb[4] = {bv.x, bv.y, bv.z, bv.w};
#pragma unroll
            for (int i = 0; i < 4; i++) {
                *(float2*)&As2[lcol + i][2 * lrow] = make_float2(va[i], va[i]);
                Bs[lcol + i][lrow] = vb[i];
            }
        }
        __syncthreads();

        // prefetch next tile into registers
        if (k0 + GBK < EMBED) {
            av = *(const float4*)(Aload + k0 + GBK);
            bv = *(const float4*)(Bload + k0 + GBK);
        }

#pragma unroll
        for (int kk = 0; kk < GBK; kk++) {
            const u64* arow = (const u64*)&As2[kk][2 * (ty * GTM)];
            u64 a2[GTM];
#pragma unroll
            for (int i = 0; i < GTM; i++) a2[i] = arow[i];
            ulonglong2 bp0 = *(const ulonglong2*)&Bs[kk][tx * GTN];
            ulonglong2 bp1 = *(const ulonglong2*)&Bs[kk][tx * GTN + 4];
            u64 b2[4] = {bp0.x, bp0.y, bp1.x, bp1.y};
#pragma unroll
            for (int i = 0; i < GTM; i++)
#pragma unroll
                for (int j = 0; j < GTN / 2; j++)
                    ffma2(acc2[i][j], a2[i], b2[j], acc2[i][j]);
        }
        __syncthreads();
    }

    // Scatter epilogue
#pragma unroll
    for (int i = 0; i < GTM; i++) {
        const int m = m0 + ty * GTM + i;
        const int s = m >> 1;            // BATCH == 2
        const int b = m & 1;
#pragma unroll
        for (int jp = 0; jp < GTN / 2; jp++) {
            float c0, c1;
            unpack2(acc2[i][jp], c0, c1);
            float cs[2] = {c0, c1};
#pragma unroll
            for (int u = 0; u < 2; u++) {
                const int f = n0 + tx * GTN + 2 * jp + u;
                float v = cs[u] + bias[f];
                const int which = f >> 10;   // 0=q 1=k 2=v
                const int e = f & 1023;
                const int h = e >> 6;
                const int d = e & 63;
                const size_t idx = ((size_t)(b * HEADS + h) * S_LEN + s) * HDIM + d;
                if (which == 0)      g_Q[idx] = v * 0.125f;
                else if (which == 1) g_K[idx] = v;
                else                 g_V[idx] = v;
            }
        }
    }
}

// ---------------------------------------------------------------------------
// Kernel 2: flash attention, 1 query/thread, f32x2 math, cp.async double buf.
// grid = (S/128, B*H), block = 128.
// ---------------------------------------------------------------------------
#define AQB 128     // queries per block
#define AKB 32      // keys per SMEM tile
#define NTILES (S_LEN / AKB)   // 64

__global__ __launch_bounds__(AQB) void attn_kernel()
{
    const int bh  = blockIdx.y;
    const int q0  = blockIdx.x * AQB;
    const int tid = threadIdx.x;

    const float* Qp = g_Q + (size_t)bh * S_LEN * HDIM;
    const float* Kp = g_K + (size_t)bh * S_LEN * HDIM;
    const float* Vp = g_V + (size_t)bh * S_LEN * HDIM;

    __shared__ float Ksh[2][AKB][HDIM];   // 2 x 8KB
    __shared__ float Vsh[2][AKB][HDIM];   // 2 x 8KB

    // my query row (pre-scaled by 0.125), as 32 f32x2 pairs
    u64 q2[HDIM / 2];
    {
        const u64* qr = (const u64*)(Qp + (size_t)(q0 + tid) * HDIM);
#pragma unroll
        for (int i = 0; i < HDIM / 2; i++) q2[i] = qr[i];
    }

    u64 acc2[HDIM / 2];
#pragma unroll
    for (int i = 0; i < HDIM / 2; i++) acc2[i] = 0ull;
    float mmax = -1e30f;
    float lsum = 0.f;

    // issue tile loads: AKB*HDIM floats = 512 float4 per matrix; 128 thr x 4
#define ISSUE_TILE(t, buf)                                                    \
    do {                                                                      \
        const float4* ksrc = (const float4*)(Kp + (size_t)(t) * AKB * HDIM);  \
        const float4* vsrc = (const float4*)(Vp + (size_t)(t) * AKB * HDIM);  \
        float4* kdst = (float4*)&Ksh[buf][0][0];                              \
        float4* vdst = (float4*)&Vsh[buf][0][0];                              \
        _Pragma("unroll")                                                     \
        for (int c = 0; c < 4; c++) {                                         \
            int i = tid + AQB * c;                                            \
            cp_async16(kdst + i, ksrc + i);                                   \
            cp_async16(vdst + i, vsrc + i);                                   \
        }                                                                     \
        cp_commit();                                                          \
    } while (0)

    ISSUE_TILE(0, 0);

    for (int t = 0; t < NTILES; t++) {
        const int buf = t & 1;
        if (t + 1 < NTILES) {
            ISSUE_TILE(t + 1, buf ^ 1);
            cp_wait<1>();
        } else {
            cp_wait<0>();
        }
        __syncthreads();

#pragma unroll 2
        for (int j = 0; j < AKB; j++) {
            const u64* kr = (const u64*)&Ksh[buf][j][0];
            // 4 independent accumulator chains for the dot product
            u64 s2a = 0ull, s2b = 0ull, s2c = 0ull, s2d = 0ull;
#pragma unroll
            for (int i = 0; i < HDIM / 2; i += 4) {
                ffma2(s2a, q2[i + 0], kr[i + 0], s2a);
                ffma2(s2b, q2[i + 1], kr[i + 1], s2b);
                ffma2(s2c, q2[i + 2], kr[i + 2], s2c);
                ffma2(s2d, q2[i + 3], kr[i + 3], s2d);
            }
            float ax, ay, bx, by, cx, cy, dx, dy;
            unpack2(s2a, ax, ay); unpack2(s2b, bx, by);
            unpack2(s2c, cx, cy); unpack2(s2d, dx, dy);
            float s = ((ax + ay) + (bx + by)) + ((cx + cy) + (dx + dy));

            if (s > mmax) {               // rare after warmup
                float scale = __expf(mmax - s);
                u64 sc2 = pack2(scale, scale);
                lsum *= scale;
#pragma unroll
                for (int i = 0; i < HDIM / 2; i++) fmul2(acc2[i], acc2[i], sc2);
                mmax = s;
            }
            float p = __expf(s - mmax);
            lsum += p;
            u64 p2 = pack2(p, p);
            const u64* vr = (const u64*)&Vsh[buf][j][0];
#pragma unroll
            for (int i = 0; i < HDIM / 2; i++)
                ffma2(acc2[i], p2, vr[i], acc2[i]);
        }
        __syncthreads();
    }
#undef ISSUE_TILE

    // write to g_Attn in [m, e] layout: m = s*B + b, e = h*64 + d
    const int b = bh / HEADS;
    const int h = bh % HEADS;
    const int s_idx = q0 + tid;
    const float inv = 1.f / lsum;
    float* outp = g_Attn + ((size_t)s_idx * BATCH + b) * EMBED + h * HDIM;
#pragma unroll
    for (int i = 0; i < HDIM / 2; i++) {
        float lo, hi;
        unpack2(acc2[i], lo, hi);
        outp[2 * i + 0] = lo * inv;
        outp[2 * i + 1] = hi * inv;
    }
}

// ---------------------------------------------------------------------------
// Kernel 3: output projection (same GEMM core), writes d_out with bias.
// ---------------------------------------------------------------------------
__global__ __launch_bounds__(256) void out_gemm_kernel(
    const float* __restrict__ W2,     // [1024, 1024]
    const float* __restrict__ bias2,  // [1024]
    float* __restrict__ out)          // [4096, 1024]
{
    __shared__ float As2[GBK][2 * GBM];
    __shared__ float Bs[GBK][GBN];

    const int tid = threadIdx.x;
    const int tx  = tid % (GBN / GTN);
    const int ty  = tid / (GBN / GTN);
    const int m0  = blockIdx.y * GBM;
    const int n0  = blockIdx.x * GBN;

    const int lrow = tid / 2;
    const int lcol = (tid % 2) * 4;

    u64 acc2[GTM][GTN / 2];
#pragma unroll
    for (int i = 0; i < GTM; i++)
#pragma unroll
        for (int j = 0; j < GTN / 2; j++) acc2[i][j] = 0ull;

    const float* Aload = g_Attn + (size_t)(m0 + lrow) * EMBED + lcol;
    const float* Bload = W2 + (size_t)(n0 + lrow) * EMBED + lcol;

    float4 av = *(const float4*)(Aload);
    float4 bv = *(const float4*)(Bload);

    for (int k0 = 0; k0 < EMBED; k0 += GBK) {
        {
            float va[4] = {av.x, av.y, av.z, av.w};
            float vb[4] = {bv.x, bv.y, bv.z, bv.w};
#pragma unroll
            for (int i = 0; i < 4; i++) {
                *(float2*)&As2[lcol + i][2 * lrow] = make_float2(va[i], va[i]);
                Bs[lcol + i][lrow] = vb[i];
            }
        }
        __syncthreads();

        if (k0 + GBK < EMBED) {
            av = *(const float4*)(Aload + k0 + GBK);
            bv = *(const float4*)(Bload + k0 + GBK);
        }

#pragma unroll
        for (int kk = 0; kk < GBK; kk++) {
            const u64* arow = (const u64*)&As2[kk][2 * (ty * GTM)];
            u64 a2[GTM];
#pragma unroll
            for (int i = 0; i < GTM; i++) a2[i] = arow[i];
            ulonglong2 bp0 = *(const ulonglong2*)&Bs[kk][tx * GTN];
            ulonglong2 bp1 = *(const ulonglong2*)&Bs[kk][tx * GTN + 4];
            u64 b2[4] = {bp0.x, bp0.y, bp1.x, bp1.y};
#pragma unroll
            for (int i = 0; i < GTM; i++)
#pragma unroll
                for (int j = 0; j < GTN / 2; j++)
                    ffma2(acc2[i][j], a2[i], b2[j], acc2[i][j]);
        }
        __syncthreads();
    }

#pragma unroll
    for (int i = 0; i < GTM; i++) {
        const int m = m0 + ty * GTM + i;
#pragma unroll
        for (int jp = 0; jp < GTN / 2; jp++) {
            float c0, c1;
            unpack2(acc2[i][jp], c0, c1);
            const int f = n0 + tx * GTN + 2 * jp;
            out[(size_t)m * EMBED + f + 0] = c0 + bias2[f + 0];
            out[(size_t)m * EMBED + f + 1] = c1 + bias2[f + 1];
        }
    }
}

// ---------------------------------------------------------------------------
extern "C" void kernel_launch(void* const* d_in, const int* in_sizes, int n_in,
                              void* d_out, int out_size)
{
    const float* x      = (const float*)d_in[0];   // [2048, 2, 1024]
    const float* w_in   = (const float*)d_in[1];   // [3072, 1024]
    const float* b_in   = (const float*)d_in[2];   // [3072]
    const float* w_out  = (const float*)d_in[3];   // [1024, 1024]
    const float* b_out  = (const float*)d_in[4];   // [1024]
    float* out = (float*)d_out;                    // [2048, 2, 1024]

    (void)in_sizes; (void)n_in; (void)out_size;

    // 1) QKV projection + head-major scatter (+ q scaling)
    {
        dim3 grid(NQKV / GBN, MROWS / GBM);   // (24, 32)
        qkv_gemm_kernel<<<grid, 256>>>(x, w_in, b_in);
    }
    // 2) flash attention per (b,h)
    {
        dim3 grid(S_LEN / AQB, BHEADS);       // (16, 32)
        attn_kernel<<<grid, AQB>>>();
    }
    // 3) output projection -> d_out
    {
        dim3 grid(EMBED / GBN, MROWS / GBM);  // (8, 32)
        out_gemm_kernel<<<grid, 256>>>(w_out, b_out, out);
    }
}